// round 8
// baseline (speedup 1.0000x reference)
#include <cuda_runtime.h>

#define N_NODES 8192
#define IN_FEAT 256
#define OUT_FEAT 64
#define NHEAD 2
#define NC (NHEAD * OUT_FEAT)     /* 128 combined output cols */
#define MASK_WPR 256              /* 8192 bits / 32 */
#define SLOPE 0.2f
#define TILE_N 32
#define MAXD 256                  /* per-row neighbor cap; mean 32, std 5.7 -> 39 sigma */

// smem transpose swizzle: 4-aligned, k-dependent -> breaks store bank conflicts
#define XSWZ(k, node) (((k) * TILE_N + (node)) ^ ((((k) >> 2) & 7) << 2))

__device__ __forceinline__ unsigned fenc(float v) {
    unsigned u = __float_as_uint(v);
    return (u >> 31) ? ~u : (u | 0x80000000u);
}
__device__ __forceinline__ float fdec(unsigned k) {
    return __uint_as_float((k >> 31) ? (k & 0x7FFFFFFFu) : ~k);
}
__device__ __forceinline__ float leaky(float v) { return (v >= 0.f) ? v : SLOPE * v; }

// ---------------- scratch (no allocations allowed) ----------------
__device__ unsigned int g_mask[N_NODES * MASK_WPR];      // 8 MB adjacency bitmask
__device__ float        g_xh[N_NODES * NC];              // 4 MB, interleaved [node][h*64+o]
__device__ float        g_s1[N_NODES * NHEAD];           // [node][h]
__device__ float        g_s2[N_NODES * NHEAD];           // [node][h]
__device__ unsigned     g_s2max[NHEAD];                  // ordered-int encoded max of s2 per head
__device__ int          g_is64;

// ---------------- kernel 1: clear bitmask (+ dtype probe + s2max reset) ----------------
__global__ void clear_mask_kernel(const void* __restrict__ ei) {
    uint4 z = make_uint4(0u, 0u, 0u, 0u);
    ((uint4*)g_mask)[blockIdx.x * blockDim.x + threadIdx.x] = z;
    if (blockIdx.x == 0 && threadIdx.x < 2) g_s2max[threadIdx.x] = 0u;  // key 0 == -inf
    if (blockIdx.x == 0 && threadIdx.x == 0) {
        // int64 node ids are always in [0, N); int32 misread as int64 is not.
        const long long* p = (const long long*)ei;
        int ok = 1;
        for (int i = 0; i < 64; i++) {
            long long v = p[i];
            if (v < 0 || v >= N_NODES) ok = 0;
        }
        g_is64 = ok;
    }
}

// ---------------- kernel 2: edges -> bitmask (dedup) ----------------
__global__ void build_mask_kernel(const void* __restrict__ ei, int E) {
    int i = blockIdx.x * blockDim.x + threadIdx.x;
    if (i >= E) return;
    int src, dst;
    if (g_is64) {
        const long long* p = (const long long*)ei;
        src = (int)p[i];
        dst = (int)p[E + i];
    } else {
        const int* p = (const int*)ei;
        src = p[i];
        dst = p[E + i];
    }
    if ((unsigned)src >= N_NODES || (unsigned)dst >= N_NODES) return;
    atomicOr(&g_mask[src * MASK_WPR + (dst >> 5)], 1u << (dst & 31));
}

// ---------------- kernel 3: xh = x @ W  +  s1/s2 (+ s2 max) epilogue ----------------
__global__ void __launch_bounds__(256) gemm_xh_kernel(
        const float* __restrict__ x, const float* __restrict__ W,
        const float* __restrict__ a1, const float* __restrict__ a2) {
    __shared__ float xs[IN_FEAT * TILE_N];   // transposed+swizzled, 32 KB
    __shared__ unsigned smax[2];
    int tid = threadIdx.x;
    int base = blockIdx.x * TILE_N;
    if (tid < 2) smax[tid] = 0u;

    for (int idx = tid; idx < TILE_N * (IN_FEAT / 4); idx += 256) {
        int node = idx >> 6;
        int kq   = idx & 63;
        float4 v = ((const float4*)(x + (size_t)(base + node) * IN_FEAT))[kq];
        int k = kq * 4;
        xs[XSWZ(k + 0, node)] = v.x;
        xs[XSWZ(k + 1, node)] = v.y;
        xs[XSWZ(k + 2, node)] = v.z;
        xs[XSWZ(k + 3, node)] = v.w;
    }
    __syncthreads();

    int tx = tid & 31;
    int ty = tid >> 5;
    int c0 = tx * 4;
    int h  = c0 >> 6;
    int o0 = c0 & 63;
    const float* Wc = W + (size_t)h * IN_FEAT * OUT_FEAT + o0;

    float acc[4][4];
#pragma unroll
    for (int n = 0; n < 4; n++)
#pragma unroll
        for (int i = 0; i < 4; i++) acc[n][i] = 0.f;

#pragma unroll 4
    for (int k = 0; k < IN_FEAT; k++) {
        float4 wv = *(const float4*)(Wc + k * OUT_FEAT);
        float4 xv = *(const float4*)&xs[XSWZ(k, ty * 4)];
        acc[0][0] = fmaf(xv.x, wv.x, acc[0][0]);
        acc[0][1] = fmaf(xv.x, wv.y, acc[0][1]);
        acc[0][2] = fmaf(xv.x, wv.z, acc[0][2]);
        acc[0][3] = fmaf(xv.x, wv.w, acc[0][3]);
        acc[1][0] = fmaf(xv.y, wv.x, acc[1][0]);
        acc[1][1] = fmaf(xv.y, wv.y, acc[1][1]);
        acc[1][2] = fmaf(xv.y, wv.z, acc[1][2]);
        acc[1][3] = fmaf(xv.y, wv.w, acc[1][3]);
        acc[2][0] = fmaf(xv.z, wv.x, acc[2][0]);
        acc[2][1] = fmaf(xv.z, wv.y, acc[2][1]);
        acc[2][2] = fmaf(xv.z, wv.z, acc[2][2]);
        acc[2][3] = fmaf(xv.z, wv.w, acc[2][3]);
        acc[3][0] = fmaf(xv.w, wv.x, acc[3][0]);
        acc[3][1] = fmaf(xv.w, wv.y, acc[3][1]);
        acc[3][2] = fmaf(xv.w, wv.z, acc[3][2]);
        acc[3][3] = fmaf(xv.w, wv.w, acc[3][3]);
    }

#pragma unroll
    for (int n = 0; n < 4; n++) {
        float4 st = make_float4(acc[n][0], acc[n][1], acc[n][2], acc[n][3]);
        *(float4*)(g_xh + (size_t)(base + ty * 4 + n) * NC + c0) = st;
    }

    float4 a1v = *(const float4*)(a1 + h * OUT_FEAT + o0);
    float4 a2v = *(const float4*)(a2 + h * OUT_FEAT + o0);
    int lane = tid & 31;
#pragma unroll
    for (int n = 0; n < 4; n++) {
        float p1 = acc[n][0] * a1v.x + acc[n][1] * a1v.y + acc[n][2] * a1v.z + acc[n][3] * a1v.w;
        float p2 = acc[n][0] * a2v.x + acc[n][1] * a2v.y + acc[n][2] * a2v.z + acc[n][3] * a2v.w;
#pragma unroll
        for (int off = 8; off; off >>= 1) {
            p1 += __shfl_xor_sync(0xFFFFFFFFu, p1, off);
            p2 += __shfl_xor_sync(0xFFFFFFFFu, p2, off);
        }
        if (lane == 0 || lane == 16) {       // lane0: head0, lane16: head1
            int node = base + ty * 4 + n;
            g_s1[node * NHEAD + h] = p1;
            g_s2[node * NHEAD + h] = p2;
            atomicMax(&smax[h], fenc(p2));
        }
    }
    __syncthreads();
    if (tid < 2) atomicMax(&g_s2max[tid], smax[tid]);
}

// ---------------- kernel 4: warp-per-row fused softmax+aggregation ----------------
// One warp per row, single loop. Lane owns 4 cols of ONE head; computes only its
// head's exp (s2 scalar load broadcasts within the 16-lane half-warp); z is
// accumulated redundantly per lane (uniform within half-warp) -> no reduction.
__global__ void __launch_bounds__(128) attention_kernel(float* __restrict__ out) {
    __shared__ unsigned short list[4][MAXD];

    int tid = threadIdx.x;
    int lane = tid & 31, wid = tid >> 5;
    int n = blockIdx.x * 4 + wid;

    // ---- mask row: lane owns 8 consecutive words ----
    const uint4* mrow = (const uint4*)(g_mask + (size_t)n * MASK_WPR);
    uint4 wa = mrow[lane * 2];
    uint4 wb = mrow[lane * 2 + 1];
    int pc = __popc(wa.x) + __popc(wa.y) + __popc(wa.z) + __popc(wa.w)
           + __popc(wb.x) + __popc(wb.y) + __popc(wb.z) + __popc(wb.w);
    int incl = pc;
#pragma unroll
    for (int off = 1; off < 32; off <<= 1) {
        int v = __shfl_up_sync(0xFFFFFFFFu, incl, off);
        if (lane >= off) incl += v;
    }
    int total = __shfl_sync(0xFFFFFFFFu, incl, 31);
    int pos = incl - pc;

    {
        unsigned words[8] = {wa.x, wa.y, wa.z, wa.w, wb.x, wb.y, wb.z, wb.w};
        int nb = lane * 256;   // lane*8 words * 32 bits
#pragma unroll
        for (int t = 0; t < 8; t++) {
            unsigned w = words[t];
            int base = nb + t * 32;
            while (w) {
                int b = __ffs(w) - 1;
                w &= w - 1;
                if (pos < MAXD) list[wid][pos] = (unsigned short)(base + b);
                pos++;
            }
        }
    }
    __syncwarp();
    int count = total < MAXD ? total : MAXD;

    if (count == 0) {
        // softmax over all-NEG row == uniform 1/N  ->  mean of xh (prob ~0, insurance)
        int c0 = lane * 4;
        float4 acc = make_float4(0.f, 0.f, 0.f, 0.f);
        for (int m = 0; m < N_NODES; m++) {
            float4 v = *(const float4*)(g_xh + (size_t)m * NC + c0);
            acc.x += v.x; acc.y += v.y; acc.z += v.z; acc.w += v.w;
        }
        float s = 1.0f / N_NODES;
        acc.x *= s; acc.y *= s; acc.z *= s; acc.w *= s;
        *(float4*)(out + (size_t)n * NC + c0) = acc;
        return;
    }

    // lane owns cols c0..c0+3, all in head h = lane>>4
    int c0 = lane * 4;
    int h  = lane >> 4;
    float s1h = g_s1[n * NHEAD + h];
    float vmh = leaky(s1h + fdec(g_s2max[h]));   // upper bound on row max (leaky monotone)
    const float* s2h = g_s2 + h;                 // s2h[2*m] = s2[m][h]
    const float* xb = g_xh + c0;
    const unsigned short* lst = list[wid];

    float z = 0.f;                               // normalizer (uniform per half-warp)
    float4 A0 = make_float4(0.f, 0.f, 0.f, 0.f);
    float4 A1 = make_float4(0.f, 0.f, 0.f, 0.f);

    int j = 0;
    for (; j + 4 <= count; j += 4) {
        int m0 = lst[j], m1 = lst[j + 1], m2 = lst[j + 2], m3 = lst[j + 3];
        float q0 = s2h[2 * m0];                  // broadcast within half-warp
        float q1 = s2h[2 * m1];
        float q2 = s2h[2 * m2];
        float q3 = s2h[2 * m3];
        float4 v0 = *(const float4*)(xb + (size_t)m0 * NC);
        float4 v1 = *(const float4*)(xb + (size_t)m1 * NC);
        float4 v2 = *(const float4*)(xb + (size_t)m2 * NC);
        float4 v3 = *(const float4*)(xb + (size_t)m3 * NC);

        float w0 = __expf(leaky(s1h + q0) - vmh);
        float w1 = __expf(leaky(s1h + q1) - vmh);
        float w2 = __expf(leaky(s1h + q2) - vmh);
        float w3 = __expf(leaky(s1h + q3) - vmh);
        z += (w0 + w1) + (w2 + w3);

        A0.x = fmaf(w0, v0.x, A0.x); A0.y = fmaf(w0, v0.y, A0.y);
        A0.z = fmaf(w0, v0.z, A0.z); A0.w = fmaf(w0, v0.w, A0.w);
        A1.x = fmaf(w1, v1.x, A1.x); A1.y = fmaf(w1, v1.y, A1.y);
        A1.z = fmaf(w1, v1.z, A1.z); A1.w = fmaf(w1, v1.w, A1.w);
        A0.x = fmaf(w2, v2.x, A0.x); A0.y = fmaf(w2, v2.y, A0.y);
        A0.z = fmaf(w2, v2.z, A0.z); A0.w = fmaf(w2, v2.w, A0.w);
        A1.x = fmaf(w3, v3.x, A1.x); A1.y = fmaf(w3, v3.y, A1.y);
        A1.z = fmaf(w3, v3.z, A1.z); A1.w = fmaf(w3, v3.w, A1.w);
    }
    for (; j < count; j++) {
        int m = lst[j];
        float q = s2h[2 * m];
        float4 v = *(const float4*)(xb + (size_t)m * NC);
        float w = __expf(leaky(s1h + q) - vmh);
        z += w;
        A0.x = fmaf(w, v.x, A0.x); A0.y = fmaf(w, v.y, A0.y);
        A0.z = fmaf(w, v.z, A0.z); A0.w = fmaf(w, v.w, A0.w);
    }

    float inv = 1.0f / z;
    float4 R;
    R.x = (A0.x + A1.x) * inv;
    R.y = (A0.y + A1.y) * inv;
    R.z = (A0.z + A1.z) * inv;
    R.w = (A0.w + A1.w) * inv;
    *(float4*)(out + (size_t)n * NC + c0) = R;
}

// ---------------- launch ----------------
extern "C" void kernel_launch(void* const* d_in, const int* in_sizes, int n_in,
                              void* d_out, int out_size) {
    const float* x  = (const float*)d_in[0];
    const void*  ei = d_in[1];
    const float* W  = (const float*)d_in[2];
    const float* a1 = (const float*)d_in[3];
    const float* a2 = (const float*)d_in[4];
    float* out = (float*)d_out;

    int E = in_sizes[1] / 2;

    clear_mask_kernel<<<(N_NODES * MASK_WPR / 4) / 256, 256>>>(ei);
    build_mask_kernel<<<(E + 255) / 256, 256>>>(ei, E);
    gemm_xh_kernel<<<N_NODES / TILE_N, 256>>>(x, W, a1, a2);
    attention_kernel<<<N_NODES / 4, 128>>>(out);
}

// round 10
// speedup vs baseline: 1.1486x; 1.1486x over previous
#include <cuda_runtime.h>

#define N_NODES 8192
#define IN_FEAT 256
#define OUT_FEAT 64
#define NHEAD 2
#define NC (NHEAD * OUT_FEAT)     /* 128 combined output cols */
#define MASK_WPR 256              /* 8192 bits / 32 */
#define SLOPE 0.2f
#define TILE_N 16                 /* gemm node tile (grid 512 -> better wave balance) */
#define MAXD 256                  /* per-row neighbor cap; mean 32, std 5.7 -> 39 sigma */

// smem transpose swizzle: 4-aligned, k-dependent -> breaks store bank conflicts
#define XSWZ(k, node) (((k) * TILE_N + (node)) ^ ((((k) >> 2) & 7) << 2))

__device__ __forceinline__ unsigned fenc(float v) {
    unsigned u = __float_as_uint(v);
    return (u >> 31) ? ~u : (u | 0x80000000u);
}
__device__ __forceinline__ float fdec(unsigned k) {
    return __uint_as_float((k >> 31) ? (k & 0x7FFFFFFFu) : ~k);
}
__device__ __forceinline__ float leaky(float v) { return (v >= 0.f) ? v : SLOPE * v; }

// ---------------- scratch (no allocations allowed) ----------------
__device__ unsigned int g_mask[N_NODES * MASK_WPR];      // 8 MB adjacency bitmask
__device__ float        g_xh[N_NODES * NC];              // 4 MB, interleaved [node][h*64+o]
__device__ float        g_s1[N_NODES * NHEAD];           // [node][h]
__device__ float        g_s2[N_NODES * NHEAD];           // [node][h]
__device__ unsigned     g_s2max[NHEAD];                  // ordered-int encoded max of s2 per head
__device__ int          g_is64;

// ---------------- kernel 1: clear bitmask (+ dtype probe + s2max reset) ----------------
__global__ void clear_mask_kernel(const void* __restrict__ ei) {
    uint4 z = make_uint4(0u, 0u, 0u, 0u);
    ((uint4*)g_mask)[blockIdx.x * blockDim.x + threadIdx.x] = z;
    if (blockIdx.x == 0 && threadIdx.x < 2) g_s2max[threadIdx.x] = 0u;  // key 0 == -inf
    if (blockIdx.x == 0 && threadIdx.x == 0) {
        // int64 node ids are always in [0, N); int32 misread as int64 is not.
        const long long* p = (const long long*)ei;
        int ok = 1;
        for (int i = 0; i < 64; i++) {
            long long v = p[i];
            if (v < 0 || v >= N_NODES) ok = 0;
        }
        g_is64 = ok;
    }
}

// ---------------- kernel 2: edges -> bitmask (dedup) ----------------
__global__ void build_mask_kernel(const void* __restrict__ ei, int E) {
    int i = blockIdx.x * blockDim.x + threadIdx.x;
    if (i >= E) return;
    int src, dst;
    if (g_is64) {
        const long long* p = (const long long*)ei;
        src = (int)p[i];
        dst = (int)p[E + i];
    } else {
        const int* p = (const int*)ei;
        src = p[i];
        dst = p[E + i];
    }
    if ((unsigned)src >= N_NODES || (unsigned)dst >= N_NODES) return;
    atomicOr(&g_mask[src * MASK_WPR + (dst >> 5)], 1u << (dst & 31));
}

// ---------------- kernel 3: xh = x @ W  +  s1/s2 (+ s2 max) epilogue ----------------
// 128 threads, tile = 16 nodes x 128 cols. Thread = 4 nodes x 4 cols.
__global__ void __launch_bounds__(128) gemm_xh_kernel(
        const float* __restrict__ x, const float* __restrict__ W,
        const float* __restrict__ a1, const float* __restrict__ a2) {
    __shared__ float xs[IN_FEAT * TILE_N];   // transposed+swizzled, 16 KB
    __shared__ unsigned smax[2];
    int tid = threadIdx.x;
    int base = blockIdx.x * TILE_N;
    if (tid < 2) smax[tid] = 0u;

    // load + transpose x tile (coalesced float4 reads along k; swizzled stores)
    for (int idx = tid; idx < TILE_N * (IN_FEAT / 4); idx += 128) {
        int node = idx >> 6;     // idx / 64
        int kq   = idx & 63;
        float4 v = ((const float4*)(x + (size_t)(base + node) * IN_FEAT))[kq];
        int k = kq * 4;
        xs[XSWZ(k + 0, node)] = v.x;
        xs[XSWZ(k + 1, node)] = v.y;
        xs[XSWZ(k + 2, node)] = v.z;
        xs[XSWZ(k + 3, node)] = v.w;
    }
    __syncthreads();

    int tx = tid & 31;
    int ty = tid >> 5;           // 0..3 -> nodes ty*4..+3
    int c0 = tx * 4;
    int h  = c0 >> 6;
    int o0 = c0 & 63;
    const float* Wc = W + (size_t)h * IN_FEAT * OUT_FEAT + o0;

    float acc[4][4];
#pragma unroll
    for (int n = 0; n < 4; n++)
#pragma unroll
        for (int i = 0; i < 4; i++) acc[n][i] = 0.f;

#pragma unroll 4
    for (int k = 0; k < IN_FEAT; k++) {
        float4 wv = *(const float4*)(Wc + k * OUT_FEAT);     // L1-resident
        float4 xv = *(const float4*)&xs[XSWZ(k, ty * 4)];    // LDS.128 broadcast in warp
        acc[0][0] = fmaf(xv.x, wv.x, acc[0][0]);
        acc[0][1] = fmaf(xv.x, wv.y, acc[0][1]);
        acc[0][2] = fmaf(xv.x, wv.z, acc[0][2]);
        acc[0][3] = fmaf(xv.x, wv.w, acc[0][3]);
        acc[1][0] = fmaf(xv.y, wv.x, acc[1][0]);
        acc[1][1] = fmaf(xv.y, wv.y, acc[1][1]);
        acc[1][2] = fmaf(xv.y, wv.z, acc[1][2]);
        acc[1][3] = fmaf(xv.y, wv.w, acc[1][3]);
        acc[2][0] = fmaf(xv.z, wv.x, acc[2][0]);
        acc[2][1] = fmaf(xv.z, wv.y, acc[2][1]);
        acc[2][2] = fmaf(xv.z, wv.z, acc[2][2]);
        acc[2][3] = fmaf(xv.z, wv.w, acc[2][3]);
        acc[3][0] = fmaf(xv.w, wv.x, acc[3][0]);
        acc[3][1] = fmaf(xv.w, wv.y, acc[3][1]);
        acc[3][2] = fmaf(xv.w, wv.z, acc[3][2]);
        acc[3][3] = fmaf(xv.w, wv.w, acc[3][3]);
    }

#pragma unroll
    for (int n = 0; n < 4; n++) {
        float4 st = make_float4(acc[n][0], acc[n][1], acc[n][2], acc[n][3]);
        *(float4*)(g_xh + (size_t)(base + ty * 4 + n) * NC + c0) = st;
    }

    float4 a1v = *(const float4*)(a1 + h * OUT_FEAT + o0);
    float4 a2v = *(const float4*)(a2 + h * OUT_FEAT + o0);
    int lane = tid & 31;
#pragma unroll
    for (int n = 0; n < 4; n++) {
        float p1 = acc[n][0] * a1v.x + acc[n][1] * a1v.y + acc[n][2] * a1v.z + acc[n][3] * a1v.w;
        float p2 = acc[n][0] * a2v.x + acc[n][1] * a2v.y + acc[n][2] * a2v.z + acc[n][3] * a2v.w;
#pragma unroll
        for (int off = 8; off; off >>= 1) {
            p1 += __shfl_xor_sync(0xFFFFFFFFu, p1, off);
            p2 += __shfl_xor_sync(0xFFFFFFFFu, p2, off);
        }
        if (lane == 0 || lane == 16) {       // lane0: head0, lane16: head1
            int node = base + ty * 4 + n;
            g_s1[node * NHEAD + h] = p1;
            g_s2[node * NHEAD + h] = p2;
            atomicMax(&smax[h], fenc(p2));
        }
    }
    __syncthreads();
    if (tid < 2) atomicMax(&g_s2max[tid], smax[tid]);
}

// ---------------- kernel 4: warp-per-row softmax + aggregation (R6 form) ----------------
// One warp per row. Pass A: exps in parallel across lanes (j strided), weights to
// smem. Pass B: pure gather+FMA, lane owns 4 cols. No __syncthreads.
__global__ void __launch_bounds__(128) attention_kernel(float* __restrict__ out) {
    __shared__ unsigned short list[4][MAXD];
    __shared__ float warr[4][2 * MAXD];    // [j][h]

    int tid = threadIdx.x;
    int lane = tid & 31, wid = tid >> 5;
    int n = blockIdx.x * 4 + wid;

    // ---- mask row: lane owns 8 consecutive words ----
    const uint4* mrow = (const uint4*)(g_mask + (size_t)n * MASK_WPR);
    uint4 wa = mrow[lane * 2];
    uint4 wb = mrow[lane * 2 + 1];
    int pc = __popc(wa.x) + __popc(wa.y) + __popc(wa.z) + __popc(wa.w)
           + __popc(wb.x) + __popc(wb.y) + __popc(wb.z) + __popc(wb.w);
    int incl = pc;
#pragma unroll
    for (int off = 1; off < 32; off <<= 1) {
        int v = __shfl_up_sync(0xFFFFFFFFu, incl, off);
        if (lane >= off) incl += v;
    }
    int total = __shfl_sync(0xFFFFFFFFu, incl, 31);
    int pos = incl - pc;

    {
        unsigned words[8] = {wa.x, wa.y, wa.z, wa.w, wb.x, wb.y, wb.z, wb.w};
        int nb = lane * 256;   // lane*8 words * 32 bits
#pragma unroll
        for (int t = 0; t < 8; t++) {
            unsigned w = words[t];
            int base = nb + t * 32;
            while (w) {
                int b = __ffs(w) - 1;
                w &= w - 1;
                if (pos < MAXD) list[wid][pos] = (unsigned short)(base + b);
                pos++;
            }
        }
    }
    __syncwarp();
    int count = total < MAXD ? total : MAXD;

    if (count == 0) {
        // softmax over all-NEG row == uniform 1/N  ->  mean of xh (prob ~0, insurance)
        int c0 = lane * 4;
        float4 acc = make_float4(0.f, 0.f, 0.f, 0.f);
        for (int m = 0; m < N_NODES; m++) {
            float4 v = *(const float4*)(g_xh + (size_t)m * NC + c0);
            acc.x += v.x; acc.y += v.y; acc.z += v.z; acc.w += v.w;
        }
        float s = 1.0f / N_NODES;
        acc.x *= s; acc.y *= s; acc.z *= s; acc.w *= s;
        *(float4*)(out + (size_t)n * NC + c0) = acc;
        return;
    }

    const float2* s1p = (const float2*)g_s1;
    const float2* s2p = (const float2*)g_s2;
    float2 s1n = s1p[n];
    // upper bound on row max via global s2 max (leaky is monotone)
    float vm0 = leaky(s1n.x + fdec(g_s2max[0]));
    float vm1 = leaky(s1n.y + fdec(g_s2max[1]));

    // ---- pass A: w = exp(e - vmax) in parallel across lanes + warp sums ----
    float z0 = 0.f, z1 = 0.f;
    for (int j = lane; j < count; j += 32) {
        int m = list[wid][j];
        float2 s2v = s2p[m];
        float w0 = __expf(leaky(s1n.x + s2v.x) - vm0);
        float w1 = __expf(leaky(s1n.y + s2v.y) - vm1);
        warr[wid][2 * j]     = w0;
        warr[wid][2 * j + 1] = w1;
        z0 += w0;
        z1 += w1;
    }
#pragma unroll
    for (int off = 16; off; off >>= 1) {
        z0 += __shfl_xor_sync(0xFFFFFFFFu, z0, off);
        z1 += __shfl_xor_sync(0xFFFFFFFFu, z1, off);
    }
    __syncwarp();
    float inv0 = 1.0f / z0;
    float inv1 = 1.0f / z1;

    // ---- pass B: lane owns cols c0..c0+3 (all in head lane>>4) ----
    int c0 = lane * 4;
    int h  = lane >> 4;
    const float* xb = g_xh + c0;
    const unsigned short* lst = list[wid];
    const float* wrr = warr[wid] + h;

    float4 A0 = make_float4(0.f, 0.f, 0.f, 0.f);
    float4 A1 = make_float4(0.f, 0.f, 0.f, 0.f);
    float4 A2 = make_float4(0.f, 0.f, 0.f, 0.f);
    float4 A3 = make_float4(0.f, 0.f, 0.f, 0.f);
    int j = 0;
    for (; j + 4 <= count; j += 4) {
        int m0 = lst[j], m1 = lst[j + 1], m2 = lst[j + 2], m3 = lst[j + 3];
        float w0 = wrr[2 * j], w1 = wrr[2 * (j + 1)];
        float w2 = wrr[2 * (j + 2)], w3 = wrr[2 * (j + 3)];
        float4 v0 = *(const float4*)(xb + (size_t)m0 * NC);
        float4 v1 = *(const float4*)(xb + (size_t)m1 * NC);
        float4 v2 = *(const float4*)(xb + (size_t)m2 * NC);
        float4 v3 = *(const float4*)(xb + (size_t)m3 * NC);
        A0.x = fmaf(w0, v0.x, A0.x); A0.y = fmaf(w0, v0.y, A0.y);
        A0.z = fmaf(w0, v0.z, A0.z); A0.w = fmaf(w0, v0.w, A0.w);
        A1.x = fmaf(w1, v1.x, A1.x); A1.y = fmaf(w1, v1.y, A1.y);
        A1.z = fmaf(w1, v1.z, A1.z); A1.w = fmaf(w1, v1.w, A1.w);
        A2.x = fmaf(w2, v2.x, A2.x); A2.y = fmaf(w2, v2.y, A2.y);
        A2.z = fmaf(w2, v2.z, A2.z); A2.w = fmaf(w2, v2.w, A2.w);
        A3.x = fmaf(w3, v3.x, A3.x); A3.y = fmaf(w3, v3.y, A3.y);
        A3.z = fmaf(w3, v3.z, A3.z); A3.w = fmaf(w3, v3.w, A3.w);
    }
    for (; j < count; j++) {
        int m = lst[j];
        float w = wrr[2 * j];
        float4 v = *(const float4*)(xb + (size_t)m * NC);
        A0.x = fmaf(w, v.x, A0.x); A0.y = fmaf(w, v.y, A0.y);
        A0.z = fmaf(w, v.z, A0.z); A0.w = fmaf(w, v.w, A0.w);
    }
    float inv = (h == 0) ? inv0 : inv1;
    float4 R;
    R.x = ((A0.x + A1.x) + (A2.x + A3.x)) * inv;
    R.y = ((A0.y + A1.y) + (A2.y + A3.y)) * inv;
    R.z = ((A0.z + A1.z) + (A2.z + A3.z)) * inv;
    R.w = ((A0.w + A1.w) + (A2.w + A3.w)) * inv;
    *(float4*)(out + (size_t)n * NC + c0) = R;
}

// ---------------- launch ----------------
extern "C" void kernel_launch(void* const* d_in, const int* in_sizes, int n_in,
                              void* d_out, int out_size) {
    const float* x  = (const float*)d_in[0];
    const void*  ei = d_in[1];
    const float* W  = (const float*)d_in[2];
    const float* a1 = (const float*)d_in[3];
    const float* a2 = (const float*)d_in[4];
    float* out = (float*)d_out;

    int E = in_sizes[1] / 2;

    clear_mask_kernel<<<(N_NODES * MASK_WPR / 4) / 256, 256>>>(ei);
    build_mask_kernel<<<(E + 255) / 256, 256>>>(ei, E);
    gemm_xh_kernel<<<N_NODES / TILE_N, 128>>>(x, W, a1, a2);
    attention_kernel<<<N_NODES / 4, 128>>>(out);
}